// round 11
// baseline (speedup 1.0000x reference)
#include <cuda_runtime.h>
#include <cstdint>

#define BB 32
#define SS 2048
#define EE 128
#define HH 8
#define DD 16
#define HD 128
#define KTOT 132
#define CACHE 256
#define WINDOW 128
#define SINKS 4

// d_out layout: [output (B*S*HD)] [new_k (B*H*128*16)] [new_v (B*H*128*16)]
#define OUT_ELEMS (BB * SS * HD)            // 8388608
#define KOFF OUT_ELEMS                      // 8388608
#define VOFF (KOFF + BB * HH * WINDOW * DD) // 8912896

// ---------------- scratch (device globals; no allocation APIs) ----------------
// g_q is pre-scaled by 0.25 * log2(e) so attention probs = exp2(q'.k)
__device__ float    g_q[(size_t)BB * SS * HD];        // 33.5 MB, layout (b,s,h*d)
__device__ float    g_ao[(size_t)BB * SS * HD];       // 33.5 MB, layout (b,s,h*d)
__device__ unsigned g_wq[4][32 * 128];                // packed ternary weights (q,k,v,o)
__device__ float    g_ws[4];                          // w_scale per weight
__device__ unsigned g_amax_x;
__device__ unsigned g_amax_o;

#define QSCALE 0.3606737602222409f  /* 0.25 * log2(e) */

// ---------------- f32x2 packed-math helpers (sm_103a) ----------------
__device__ __forceinline__ unsigned long long f2_mul(unsigned long long a, unsigned long long b) {
    unsigned long long d;
    asm("mul.rn.f32x2 %0,%1,%2;" : "=l"(d) : "l"(a), "l"(b));
    return d;
}
__device__ __forceinline__ unsigned long long f2_fma(unsigned long long a, unsigned long long b,
                                                     unsigned long long c) {
    unsigned long long d;
    asm("fma.rn.f32x2 %0,%1,%2,%3;" : "=l"(d) : "l"(a), "l"(b), "l"(c));
    return d;
}
__device__ __forceinline__ unsigned long long f2_add(unsigned long long a, unsigned long long b) {
    unsigned long long d;
    asm("add.rn.f32x2 %0,%1,%2;" : "=l"(d) : "l"(a), "l"(b));
    return d;
}
__device__ __forceinline__ unsigned long long f2_pack(float lo, float hi) {
    unsigned long long d;
    asm("mov.b64 %0,{%1,%2};" : "=l"(d) : "f"(lo), "f"(hi));
    return d;
}
__device__ __forceinline__ float2 f2_unpack(unsigned long long v) {
    float2 r;
    asm("mov.b64 {%0,%1},%2;" : "=f"(r.x), "=f"(r.y) : "l"(v));
    return r;
}
__device__ __forceinline__ float fast_ex2(float x) {
    float r;
    asm("ex2.approx.ftz.f32 %0,%1;" : "=f"(r) : "f"(x));
    return r;
}

// ---------------- helpers ----------------
__device__ __forceinline__ unsigned quant4(float4 v, float is_inv) {
    int a = __float2int_rn(fminf(fmaxf(v.x * is_inv, -128.f), 127.f));
    int b = __float2int_rn(fminf(fmaxf(v.y * is_inv, -128.f), 127.f));
    int c = __float2int_rn(fminf(fmaxf(v.z * is_inv, -128.f), 127.f));
    int d = __float2int_rn(fminf(fmaxf(v.w * is_inv, -128.f), 127.f));
    return (unsigned)(a & 0xFF) | ((unsigned)(b & 0xFF) << 8) |
           ((unsigned)(c & 0xFF) << 16) | ((unsigned)(d & 0xFF) << 24);
}

// ---------------- kernel 1: w_scale + ternarize + pack (4 blocks) + init -----
__global__ __launch_bounds__(256) void k_prep(const float* qw, const float* kw,
                                              const float* vw, const float* ow) {
    int bw = blockIdx.x;
    if (bw == 0 && threadIdx.x == 0) { g_amax_x = 0u; g_amax_o = 0u; }
    const float* w = (bw == 0) ? qw : (bw == 1) ? kw : (bw == 2) ? vw : ow;
    __shared__ float red[256];
    __shared__ float ws_s;
    int t = threadIdx.x;
    float s = 0.f;
    for (int i = t; i < 16384; i += 256) s += fabsf(w[i]);
    red[t] = s;
    __syncthreads();
    for (int o = 128; o > 0; o >>= 1) {
        if (t < o) red[t] += red[t + o];
        __syncthreads();
    }
    if (t == 0) { ws_s = red[0] / 16384.0f; g_ws[bw] = ws_s; }
    __syncthreads();
    float thr = 0.5f * ws_s;
    int c = t >> 1, half = t & 1;
    for (int i = 0; i < 16; i++) {
        int kk = half * 16 + i;
        float4 wv = *(const float4*)(w + c * 128 + kk * 4);
        int t0 = (fabsf(wv.x) > thr) ? (wv.x > 0.f ? 1 : -1) : 0;
        int t1 = (fabsf(wv.y) > thr) ? (wv.y > 0.f ? 1 : -1) : 0;
        int t2 = (fabsf(wv.z) > thr) ? (wv.z > 0.f ? 1 : -1) : 0;
        int t3 = (fabsf(wv.w) > thr) ? (wv.w > 0.f ? 1 : -1) : 0;
        unsigned p = (unsigned)(t0 & 0xFF) | ((unsigned)(t1 & 0xFF) << 8) |
                     ((unsigned)(t2 & 0xFF) << 16) | ((unsigned)(t3 & 0xFF) << 24);
        g_wq[bw][kk * 128 + c] = p;
    }
}

// ---------------- kernel 2: abs-max over x ----------------
__global__ __launch_bounds__(256) void k_amax(const float* x, int n4) {
    int idx = blockIdx.x * blockDim.x + threadIdx.x;
    int stride = gridDim.x * blockDim.x;
    float m = 0.f;
    const float4* x4 = (const float4*)x;
    for (int i = idx; i < n4; i += stride) {
        float4 v = x4[i];
        m = fmaxf(m, fmaxf(fmaxf(fabsf(v.x), fabsf(v.y)), fmaxf(fabsf(v.z), fabsf(v.w))));
    }
    for (int o = 16; o; o >>= 1) m = fmaxf(m, __shfl_xor_sync(0xFFFFFFFFu, m, o));
    if ((threadIdx.x & 31) == 0) atomicMax(&g_amax_x, __float_as_uint(m));
}

// ---------------- shared GEMM core: 32 rows x 128 cols, dp4a ----------------
// 256 threads. warp w owns rows 4w..4w+3; lane owns cols 4*lane..4*lane+3
#define DP(a, b, c) c = __dp4a((int)(a), (int)(b), c)

__device__ __forceinline__ void bitgemm_core(const float* xbase, const unsigned* wq_g,
                                             float is_inv, unsigned* xq_s, unsigned* wq_s,
                                             int (&acc)[4][4]) {
    int t = threadIdx.x;
    {
        int row = t >> 3, seg = t & 7;
        const float4* src = (const float4*)(xbase + row * 128 + seg * 16);
        uint4 pk;
        pk.x = quant4(src[0], is_inv);
        pk.y = quant4(src[1], is_inv);
        pk.z = quant4(src[2], is_inv);
        pk.w = quant4(src[3], is_inv);
        *(uint4*)(xq_s + row * 32 + seg * 4) = pk;
    }
    {
        const uint4* src = (const uint4*)wq_g;
        uint4* dst = (uint4*)wq_s;
#pragma unroll
        for (int i = 0; i < 4; i++) dst[t + i * 256] = src[t + i * 256];
    }
    __syncthreads();
    int warp = t >> 5, lane = t & 31;
#pragma unroll
    for (int rr = 0; rr < 4; rr++)
#pragma unroll
        for (int cc = 0; cc < 4; cc++) acc[rr][cc] = 0;
    const uint4* x4 = (const uint4*)xq_s;  // [row*8 + kk/4]
    const uint4* w4 = (const uint4*)wq_s;  // [kk*32 + lane] = cols 4l..4l+3 at word kk
#pragma unroll
    for (int kk = 0; kk < 32; kk += 4) {
        uint4 xr0 = x4[(warp * 4 + 0) * 8 + (kk >> 2)];
        uint4 xr1 = x4[(warp * 4 + 1) * 8 + (kk >> 2)];
        uint4 xr2 = x4[(warp * 4 + 2) * 8 + (kk >> 2)];
        uint4 xr3 = x4[(warp * 4 + 3) * 8 + (kk >> 2)];
        uint4 w0 = w4[(kk + 0) * 32 + lane];
        uint4 w1 = w4[(kk + 1) * 32 + lane];
        uint4 w2 = w4[(kk + 2) * 32 + lane];
        uint4 w3 = w4[(kk + 3) * 32 + lane];
        DP(xr0.x, w0.x, acc[0][0]); DP(xr0.y, w1.x, acc[0][0]); DP(xr0.z, w2.x, acc[0][0]); DP(xr0.w, w3.x, acc[0][0]);
        DP(xr0.x, w0.y, acc[0][1]); DP(xr0.y, w1.y, acc[0][1]); DP(xr0.z, w2.y, acc[0][1]); DP(xr0.w, w3.y, acc[0][1]);
        DP(xr0.x, w0.z, acc[0][2]); DP(xr0.y, w1.z, acc[0][2]); DP(xr0.z, w2.z, acc[0][2]); DP(xr0.w, w3.z, acc[0][2]);
        DP(xr0.x, w0.w, acc[0][3]); DP(xr0.y, w1.w, acc[0][3]); DP(xr0.z, w2.w, acc[0][3]); DP(xr0.w, w3.w, acc[0][3]);
        DP(xr1.x, w0.x, acc[1][0]); DP(xr1.y, w1.x, acc[1][0]); DP(xr1.z, w2.x, acc[1][0]); DP(xr1.w, w3.x, acc[1][0]);
        DP(xr1.x, w0.y, acc[1][1]); DP(xr1.y, w1.y, acc[1][1]); DP(xr1.z, w2.y, acc[1][1]); DP(xr1.w, w3.y, acc[1][1]);
        DP(xr1.x, w0.z, acc[1][2]); DP(xr1.y, w1.z, acc[1][2]); DP(xr1.z, w2.z, acc[1][2]); DP(xr1.w, w3.z, acc[1][2]);
        DP(xr1.x, w0.w, acc[1][3]); DP(xr1.y, w1.w, acc[1][3]); DP(xr1.z, w2.w, acc[1][3]); DP(xr1.w, w3.w, acc[1][3]);
        DP(xr2.x, w0.x, acc[2][0]); DP(xr2.y, w1.x, acc[2][0]); DP(xr2.z, w2.x, acc[2][0]); DP(xr2.w, w3.x, acc[2][0]);
        DP(xr2.x, w0.y, acc[2][1]); DP(xr2.y, w1.y, acc[2][1]); DP(xr2.z, w2.y, acc[2][1]); DP(xr2.w, w3.y, acc[2][1]);
        DP(xr2.x, w0.z, acc[2][2]); DP(xr2.y, w1.z, acc[2][2]); DP(xr2.z, w2.z, acc[2][2]); DP(xr2.w, w3.z, acc[2][2]);
        DP(xr2.x, w0.w, acc[2][3]); DP(xr2.y, w1.w, acc[2][3]); DP(xr2.z, w2.w, acc[2][3]); DP(xr2.w, w3.w, acc[2][3]);
        DP(xr3.x, w0.x, acc[3][0]); DP(xr3.y, w1.x, acc[3][0]); DP(xr3.z, w2.x, acc[3][0]); DP(xr3.w, w3.x, acc[3][0]);
        DP(xr3.x, w0.y, acc[3][1]); DP(xr3.y, w1.y, acc[3][1]); DP(xr3.z, w2.y, acc[3][1]); DP(xr3.w, w3.y, acc[3][1]);
        DP(xr3.x, w0.z, acc[3][2]); DP(xr3.y, w1.z, acc[3][2]); DP(xr3.z, w2.z, acc[3][2]); DP(xr3.w, w3.z, acc[3][2]);
        DP(xr3.x, w0.w, acc[3][3]); DP(xr3.y, w1.w, acc[3][3]); DP(xr3.z, w2.w, acc[3][3]); DP(xr3.w, w3.w, acc[3][3]);
    }
}

// ---------------- kernel 3: Q + K/V projections in one launch ----------------
// blocks [0, 2048): Q rows; [2048, 2176): K rows; [2176, 2304): V rows
__global__ __launch_bounds__(256) void k_proj(const float* x, const float* qb,
                                              const float* kb, const float* vb,
                                              float* out) {
    __shared__ unsigned xq_s[32 * 32];
    __shared__ unsigned wq_s[32 * 128];
    int blk = blockIdx.x;
    float amax = __uint_as_float(g_amax_x);
    float is_inv = __fdiv_rn(127.0f, amax);
    float is = amax * (1.0f / 127.0f);
    int warp = threadIdx.x >> 5, lane = threadIdx.x & 31;
    int c0 = lane * 4;
    int acc[4][4];

    if (blk < 2048) {  // ---- Q ---- (pre-scaled by 0.25*log2e for exp2-domain attn)
        int row0 = blk * 32;
        float sc = g_ws[0] * is;
        bitgemm_core(x + (size_t)row0 * 128, g_wq[0], is_inv, xq_s, wq_s, acc);
        float4 bias = *(const float4*)(qb + c0);
#pragma unroll
        for (int rr = 0; rr < 4; rr++) {
            int r = row0 + warp * 4 + rr;
            float4 o;
            o.x = ((float)acc[rr][0] * sc + bias.x) * QSCALE;
            o.y = ((float)acc[rr][1] * sc + bias.y) * QSCALE;
            o.z = ((float)acc[rr][2] * sc + bias.z) * QSCALE;
            o.w = ((float)acc[rr][3] * sc + bias.w) * QSCALE;
            *(float4*)(g_q + (size_t)r * 128 + c0) = o;
        }
    } else {  // ---- K or V, last 128 tokens of each batch ----
        int which = (blk >= 2176) ? 1 : 0;
        int row0 = (blk - (which ? 2176 : 2048)) * 32;  // r in [0,4096)
        int b = row0 >> 7, i0 = row0 & 127;
        const float* xbase = x + (((size_t)b * SS) + (SS - WINDOW) + i0) * EE;
        float sc = g_ws[1 + which] * is;
        const float* bias_p = which ? vb : kb;
        size_t base = which ? (size_t)VOFF : (size_t)KOFF;
        bitgemm_core(xbase, g_wq[1 + which], is_inv, xq_s, wq_s, acc);
        float4 bias = *(const float4*)(bias_p + c0);
        int h = c0 >> 4, d0 = c0 & 15;
#pragma unroll
        for (int rr = 0; rr < 4; rr++) {
            int r = row0 + warp * 4 + rr;
            int b2 = r >> 7, ii = r & 127;
            float4 o;
            o.x = (float)acc[rr][0] * sc + bias.x;
            o.y = (float)acc[rr][1] * sc + bias.y;
            o.z = (float)acc[rr][2] * sc + bias.z;
            o.w = (float)acc[rr][3] * sc + bias.w;
            *(float4*)(out + base + (((size_t)(b2 * HH + h)) * WINDOW + ii) * DD + d0) = o;
        }
    }
}

// ---------------- attention inner machinery (no-max softmax, exp2 domain) ----
#define NEG_INF __int_as_float(0xff800000)

struct AttState {
    unsigned long long q[8];
    unsigned long long a[8];
};

__device__ __forceinline__ void att_load_q(AttState& st, const float* qptr) {
    const ulonglong2* qp = (const ulonglong2*)qptr;
    ulonglong2 q01 = qp[0], q23 = qp[1], q45 = qp[2], q67 = qp[3];
    st.q[0] = q01.x; st.q[1] = q01.y; st.q[2] = q23.x; st.q[3] = q23.y;
    st.q[4] = q45.x; st.q[5] = q45.y; st.q[6] = q67.x; st.q[7] = q67.y;
#pragma unroll
    for (int i = 0; i < 8; i++) st.a[i] = 0ull;
}

// first-half score: dims 0..7 (kA = dims 0-3, kB = dims 4-7)
__device__ __forceinline__ void score_h1(const AttState& st, const ulonglong2& kA,
                                         const ulonglong2& kB,
                                         unsigned long long& d0, unsigned long long& d1) {
    d0 = f2_mul(st.q[0], kA.x);
    d1 = f2_mul(st.q[1], kA.y);
    d0 = f2_fma(st.q[2], kB.x, d0);
    d1 = f2_fma(st.q[3], kB.y, d1);
}
// second-half score: dims 8..15
__device__ __forceinline__ void score_h2(const AttState& st, const ulonglong2& kC,
                                         const ulonglong2& kD,
                                         unsigned long long& d0, unsigned long long& d1) {
    d0 = f2_fma(st.q[4], kC.x, d0);
    d1 = f2_fma(st.q[5], kC.y, d1);
    d0 = f2_fma(st.q[6], kD.x, d0);
    d1 = f2_fma(st.q[7], kD.y, d1);
}
// accumulate 8 output dims starting at a[base] from two V quads
__device__ __forceinline__ void accum_h(AttState& st, int base, unsigned long long p2,
                                        const ulonglong2& vA, const ulonglong2& vB) {
    st.a[base + 0] = f2_fma(p2, vA.x, st.a[base + 0]);
    st.a[base + 1] = f2_fma(p2, vA.y, st.a[base + 1]);
    st.a[base + 2] = f2_fma(p2, vB.x, st.a[base + 2]);
    st.a[base + 3] = f2_fma(p2, vB.y, st.a[base + 3]);
}

__device__ __forceinline__ float att_finish(AttState& st, float l, float* optr) {
    float inv = 1.0f / l;
    unsigned long long inv2 = f2_pack(inv, inv);
    float mx = 0.f;
#pragma unroll
    for (int i = 0; i < 8; i++) {
        st.a[i] = f2_mul(st.a[i], inv2);
        float2 u = f2_unpack(st.a[i]);
        mx = fmaxf(mx, fmaxf(fabsf(u.x), fabsf(u.y)));
    }
    ulonglong2* op = (ulonglong2*)optr;
    op[0] = make_ulonglong2(st.a[0], st.a[1]);
    op[1] = make_ulonglong2(st.a[2], st.a[3]);
    op[2] = make_ulonglong2(st.a[4], st.a[5]);
    op[3] = make_ulonglong2(st.a[6], st.a[7]);
    return mx;
}

// ---------------- kernel 5: attention, 256 thr, 2 q/thread, 3 CTAs/SM --------
// grid: (SS/512, H, B). Thread t handles queries chunk*512+t and +256.
__global__ __launch_bounds__(256, 3) void k_attn(const float* cached_k, const float* cached_v,
                                                 const float* outbuf) {
    __shared__ __align__(16) float ks[KTOT * DD];
    __shared__ __align__(16) float vs[KTOT * DD];
    int b = blockIdx.z, h = blockIdx.y, chunk = blockIdx.x;
    int t = threadIdx.x;
    size_t bh = (size_t)(b * HH + h);
    {
        // vectorized fill: sinks (4 rows = 16 float4), window (128 rows = 512 float4)
        const float4* kc4 = (const float4*)(cached_k + bh * CACHE * DD);
        const float4* vc4 = (const float4*)(cached_v + bh * CACHE * DD);
        const float4* kn4 = (const float4*)(outbuf + KOFF + bh * WINDOW * DD);
        const float4* vn4 = (const float4*)(outbuf + VOFF + bh * WINDOW * DD);
        float4* ks4 = (float4*)ks;
        float4* vs4 = (float4*)vs;
        if (t < 16) {
            ks4[t] = kc4[t];
            vs4[t] = vc4[t];
        }
#pragma unroll
        for (int i = 0; i < 2; i++) {
            int idx = t + i * 256;
            ks4[16 + idx] = kn4[idx];
            vs4[16 + idx] = vn4[idx];
        }
    }
    __syncthreads();

    int s0 = chunk * 512 + t;
    int s1 = s0 + 256;
    const float* qbase = g_q + ((size_t)b * SS) * HD + h * DD;
    AttState st0, st1;
    att_load_q(st0, qbase + (size_t)s0 * HD);
    att_load_q(st1, qbase + (size_t)s1 * HD);
    unsigned long long l01 = 0ull;  // packed (l0, l1)

    const ulonglong2* k2 = (const ulonglong2*)ks;
    const ulonglong2* v2 = (const ulonglong2*)vs;

    if (chunk != 0) {
        // full: both queries attend to all 132 keys
#pragma unroll 2
        for (int j = 0; j < KTOT; j++) {
            unsigned long long d00, d01, d10, d11;
            {
                ulonglong2 kA = k2[j * 4 + 0], kB = k2[j * 4 + 1];
                score_h1(st0, kA, kB, d00, d01);
                score_h1(st1, kA, kB, d10, d11);
            }
            {
                ulonglong2 kC = k2[j * 4 + 2], kD = k2[j * 4 + 3];
                score_h2(st0, kC, kD, d00, d01);
                score_h2(st1, kC, kD, d10, d11);
            }
            float2 ds0 = f2_unpack(f2_add(d00, d01));
            float2 ds1 = f2_unpack(f2_add(d10, d11));
            float p0 = fast_ex2(ds0.x + ds0.y);
            float p1 = fast_ex2(ds1.x + ds1.y);
            l01 = f2_add(l01, f2_pack(p0, p1));
            unsigned long long p00 = f2_pack(p0, p0);
            unsigned long long p11 = f2_pack(p1, p1);
            {
                ulonglong2 vA = v2[j * 4 + 0], vB = v2[j * 4 + 1];
                accum_h(st0, 0, p00, vA, vB);
                accum_h(st1, 0, p11, vA, vB);
            }
            {
                ulonglong2 vC = v2[j * 4 + 2], vD = v2[j * 4 + 3];
                accum_h(st0, 4, p00, vC, vD);
                accum_h(st1, 4, p11, vC, vD);
            }
        }
    } else {
        // chunk 0: query s0 = t in [0,255] may be causal-ragged; s1 >= 256 is full
        int jmax0 = min(s0, KTOT - 1);
        for (int j = 0; j < KTOT; j++) {
            unsigned long long d00, d01, d10, d11;
            {
                ulonglong2 kA = k2[j * 4 + 0], kB = k2[j * 4 + 1];
                score_h1(st0, kA, kB, d00, d01);
                score_h1(st1, kA, kB, d10, d11);
            }
            {
                ulonglong2 kC = k2[j * 4 + 2], kD = k2[j * 4 + 3];
                score_h2(st0, kC, kD, d00, d01);
                score_h2(st1, kC, kD, d10, d11);
            }
            float2 ds0 = f2_unpack(f2_add(d00, d01));
            float2 ds1 = f2_unpack(f2_add(d10, d11));
            float sc0 = ds0.x + ds0.y;
            sc0 = (j <= jmax0) ? sc0 : NEG_INF;  // ex2(-inf) = 0 contribution
            float p0 = fast_ex2(sc0);
            float p1 = fast_ex2(ds1.x + ds1.y);
            l01 = f2_add(l01, f2_pack(p0, p1));
            unsigned long long p00 = f2_pack(p0, p0);
            unsigned long long p11 = f2_pack(p1, p1);
            {
                ulonglong2 vA = v2[j * 4 + 0], vB = v2[j * 4 + 1];
                accum_h(st0, 0, p00, vA, vB);
                accum_h(st1, 0, p11, vA, vB);
            }
            {
                ulonglong2 vC = v2[j * 4 + 2], vD = v2[j * 4 + 3];
                accum_h(st0, 4, p00, vC, vD);
                accum_h(st1, 4, p11, vC, vD);
            }
        }
    }

    float2 l = f2_unpack(l01);
    float* aob = g_ao + ((size_t)b * SS) * HD + h * DD;
    float mx0 = att_finish(st0, l.x, aob + (size_t)s0 * HD);
    float mx1 = att_finish(st1, l.y, aob + (size_t)s1 * HD);
    float mx = fmaxf(mx0, mx1);
    for (int o = 16; o; o >>= 1) mx = fmaxf(mx, __shfl_xor_sync(0xFFFFFFFFu, mx, o));
    if ((t & 31) == 0) atomicMax(&g_amax_o, __float_as_uint(mx));
}

// ---------------- kernel 6: O projection ----------------
__global__ __launch_bounds__(256) void k_oproj(const float* ob, float* out) {
    __shared__ unsigned xq_s[32 * 32];
    __shared__ unsigned wq_s[32 * 128];
    int row0 = blockIdx.x * 32;
    float amax = __uint_as_float(g_amax_o);
    float is_inv = __fdiv_rn(127.0f, amax);
    float sc = g_ws[3] * (amax * (1.0f / 127.0f));
    int acc[4][4];
    bitgemm_core(g_ao + (size_t)row0 * 128, g_wq[3], is_inv, xq_s, wq_s, acc);
    int warp = threadIdx.x >> 5, lane = threadIdx.x & 31;
    int c0 = lane * 4;
    float4 bias = *(const float4*)(ob + c0);
#pragma unroll
    for (int rr = 0; rr < 4; rr++) {
        int r = row0 + warp * 4 + rr;
        float4 o;
        o.x = (float)acc[rr][0] * sc + bias.x;
        o.y = (float)acc[rr][1] * sc + bias.y;
        o.z = (float)acc[rr][2] * sc + bias.z;
        o.w = (float)acc[rr][3] * sc + bias.w;
        *(float4*)(out + (size_t)r * 128 + c0) = o;
    }
}

// ---------------- launcher ----------------
extern "C" void kernel_launch(void* const* d_in, const int* in_sizes, int n_in,
                              void* d_out, int out_size) {
    const float* x  = (const float*)d_in[0];
    const float* ck = (const float*)d_in[1];
    const float* cv = (const float*)d_in[2];
    const float* qb = (const float*)d_in[4];
    const float* kb = (const float*)d_in[6];
    const float* vb = (const float*)d_in[8];
    const float* ob = (const float*)d_in[10];
    const float* qw = (const float*)d_in[3];
    const float* kw = (const float*)d_in[5];
    const float* vw = (const float*)d_in[7];
    const float* ow = (const float*)d_in[9];
    float* out = (float*)d_out;

    k_prep<<<4, 256>>>(qw, kw, vw, ow);
    k_amax<<<1024, 256>>>(x, (BB * SS * EE) / 4);
    k_proj<<<2048 + 256, 256>>>(x, qb, kb, vb, out);
    k_attn<<<dim3(SS / 512, HH, BB), 256>>>(ck, cv, out);
    k_oproj<<<(BB * SS) / 32, 256>>>(ob, out);
}

// round 12
// speedup vs baseline: 1.1159x; 1.1159x over previous
#include <cuda_runtime.h>
#include <cstdint>

#define BB 32
#define SS 2048
#define EE 128
#define HH 8
#define DD 16
#define HD 128
#define KTOT 132
#define CACHE 256
#define WINDOW 128
#define SINKS 4

// d_out layout: [output (B*S*HD)] [new_k (B*H*128*16)] [new_v (B*H*128*16)]
#define OUT_ELEMS (BB * SS * HD)            // 8388608
#define KOFF OUT_ELEMS                      // 8388608
#define VOFF (KOFF + BB * HH * WINDOW * DD) // 8912896

// ---------------- scratch (device globals; no allocation APIs) ----------------
// g_q is pre-scaled by 0.25 * log2(e) so attention probs = exp2(q'.k)
__device__ float    g_q[(size_t)BB * SS * HD];        // 33.5 MB, layout (b,s,h*d)
__device__ float    g_ao[(size_t)BB * SS * HD];       // 33.5 MB, layout (b,s,h*d)
__device__ unsigned g_wq[4][32 * 128];                // packed ternary weights (q,k,v,o)
__device__ float    g_ws[4];                          // w_scale per weight
__device__ unsigned g_amax_x;
__device__ unsigned g_amax_o;

#define QSCALE 0.3606737602222409f  /* 0.25 * log2(e) */

// ---------------- f32x2 packed-math helpers (sm_103a) ----------------
__device__ __forceinline__ unsigned long long f2_mul(unsigned long long a, unsigned long long b) {
    unsigned long long d;
    asm("mul.rn.f32x2 %0,%1,%2;" : "=l"(d) : "l"(a), "l"(b));
    return d;
}
__device__ __forceinline__ unsigned long long f2_fma(unsigned long long a, unsigned long long b,
                                                     unsigned long long c) {
    unsigned long long d;
    asm("fma.rn.f32x2 %0,%1,%2,%3;" : "=l"(d) : "l"(a), "l"(b), "l"(c));
    return d;
}
__device__ __forceinline__ unsigned long long f2_add(unsigned long long a, unsigned long long b) {
    unsigned long long d;
    asm("add.rn.f32x2 %0,%1,%2;" : "=l"(d) : "l"(a), "l"(b));
    return d;
}
__device__ __forceinline__ unsigned long long f2_pack(float lo, float hi) {
    unsigned long long d;
    asm("mov.b64 %0,{%1,%2};" : "=l"(d) : "f"(lo), "f"(hi));
    return d;
}
__device__ __forceinline__ float2 f2_unpack(unsigned long long v) {
    float2 r;
    asm("mov.b64 {%0,%1},%2;" : "=f"(r.x), "=f"(r.y) : "l"(v));
    return r;
}
__device__ __forceinline__ float fast_ex2(float x) {
    float r;
    asm("ex2.approx.ftz.f32 %0,%1;" : "=f"(r) : "f"(x));
    return r;
}

// ---------------- helpers ----------------
__device__ __forceinline__ unsigned quant4(float4 v, float is_inv) {
    int a = __float2int_rn(fminf(fmaxf(v.x * is_inv, -128.f), 127.f));
    int b = __float2int_rn(fminf(fmaxf(v.y * is_inv, -128.f), 127.f));
    int c = __float2int_rn(fminf(fmaxf(v.z * is_inv, -128.f), 127.f));
    int d = __float2int_rn(fminf(fmaxf(v.w * is_inv, -128.f), 127.f));
    return (unsigned)(a & 0xFF) | ((unsigned)(b & 0xFF) << 8) |
           ((unsigned)(c & 0xFF) << 16) | ((unsigned)(d & 0xFF) << 24);
}

// ---------------- kernel 1: w_scale + ternarize + pack (4 blocks) + init -----
__global__ __launch_bounds__(256) void k_prep(const float* qw, const float* kw,
                                              const float* vw, const float* ow) {
    int bw = blockIdx.x;
    if (bw == 0 && threadIdx.x == 0) { g_amax_x = 0u; g_amax_o = 0u; }
    const float* w = (bw == 0) ? qw : (bw == 1) ? kw : (bw == 2) ? vw : ow;
    __shared__ float red[256];
    __shared__ float ws_s;
    int t = threadIdx.x;
    float s = 0.f;
    for (int i = t; i < 16384; i += 256) s += fabsf(w[i]);
    red[t] = s;
    __syncthreads();
    for (int o = 128; o > 0; o >>= 1) {
        if (t < o) red[t] += red[t + o];
        __syncthreads();
    }
    if (t == 0) { ws_s = red[0] / 16384.0f; g_ws[bw] = ws_s; }
    __syncthreads();
    float thr = 0.5f * ws_s;
    int c = t >> 1, half = t & 1;
    for (int i = 0; i < 16; i++) {
        int kk = half * 16 + i;
        float4 wv = *(const float4*)(w + c * 128 + kk * 4);
        int t0 = (fabsf(wv.x) > thr) ? (wv.x > 0.f ? 1 : -1) : 0;
        int t1 = (fabsf(wv.y) > thr) ? (wv.y > 0.f ? 1 : -1) : 0;
        int t2 = (fabsf(wv.z) > thr) ? (wv.z > 0.f ? 1 : -1) : 0;
        int t3 = (fabsf(wv.w) > thr) ? (wv.w > 0.f ? 1 : -1) : 0;
        unsigned p = (unsigned)(t0 & 0xFF) | ((unsigned)(t1 & 0xFF) << 8) |
                     ((unsigned)(t2 & 0xFF) << 16) | ((unsigned)(t3 & 0xFF) << 24);
        g_wq[bw][kk * 128 + c] = p;
    }
}

// ---------------- kernel 2: abs-max over x ----------------
__global__ __launch_bounds__(256) void k_amax(const float* x, int n4) {
    int idx = blockIdx.x * blockDim.x + threadIdx.x;
    int stride = gridDim.x * blockDim.x;
    float m = 0.f;
    const float4* x4 = (const float4*)x;
    for (int i = idx; i < n4; i += stride) {
        float4 v = x4[i];
        m = fmaxf(m, fmaxf(fmaxf(fabsf(v.x), fabsf(v.y)), fmaxf(fabsf(v.z), fabsf(v.w))));
    }
    for (int o = 16; o; o >>= 1) m = fmaxf(m, __shfl_xor_sync(0xFFFFFFFFu, m, o));
    if ((threadIdx.x & 31) == 0) atomicMax(&g_amax_x, __float_as_uint(m));
}

// ---------------- shared GEMM core: 32 rows x 128 cols, dp4a ----------------
// 256 threads. warp w owns rows 4w..4w+3; lane owns cols 4*lane..4*lane+3
#define DP(a, b, c) c = __dp4a((int)(a), (int)(b), c)

__device__ __forceinline__ void bitgemm_core(const float* xbase, const unsigned* wq_g,
                                             float is_inv, unsigned* xq_s, unsigned* wq_s,
                                             int (&acc)[4][4]) {
    int t = threadIdx.x;
    {
        int row = t >> 3, seg = t & 7;
        const float4* src = (const float4*)(xbase + row * 128 + seg * 16);
        uint4 pk;
        pk.x = quant4(src[0], is_inv);
        pk.y = quant4(src[1], is_inv);
        pk.z = quant4(src[2], is_inv);
        pk.w = quant4(src[3], is_inv);
        *(uint4*)(xq_s + row * 32 + seg * 4) = pk;
    }
    {
        const uint4* src = (const uint4*)wq_g;
        uint4* dst = (uint4*)wq_s;
#pragma unroll
        for (int i = 0; i < 4; i++) dst[t + i * 256] = src[t + i * 256];
    }
    __syncthreads();
    int warp = t >> 5, lane = t & 31;
#pragma unroll
    for (int rr = 0; rr < 4; rr++)
#pragma unroll
        for (int cc = 0; cc < 4; cc++) acc[rr][cc] = 0;
    const uint4* x4 = (const uint4*)xq_s;  // [row*8 + kk/4]
    const uint4* w4 = (const uint4*)wq_s;  // [kk*32 + lane] = cols 4l..4l+3 at word kk
#pragma unroll
    for (int kk = 0; kk < 32; kk += 4) {
        uint4 xr0 = x4[(warp * 4 + 0) * 8 + (kk >> 2)];
        uint4 xr1 = x4[(warp * 4 + 1) * 8 + (kk >> 2)];
        uint4 xr2 = x4[(warp * 4 + 2) * 8 + (kk >> 2)];
        uint4 xr3 = x4[(warp * 4 + 3) * 8 + (kk >> 2)];
        uint4 w0 = w4[(kk + 0) * 32 + lane];
        uint4 w1 = w4[(kk + 1) * 32 + lane];
        uint4 w2 = w4[(kk + 2) * 32 + lane];
        uint4 w3 = w4[(kk + 3) * 32 + lane];
        DP(xr0.x, w0.x, acc[0][0]); DP(xr0.y, w1.x, acc[0][0]); DP(xr0.z, w2.x, acc[0][0]); DP(xr0.w, w3.x, acc[0][0]);
        DP(xr0.x, w0.y, acc[0][1]); DP(xr0.y, w1.y, acc[0][1]); DP(xr0.z, w2.y, acc[0][1]); DP(xr0.w, w3.y, acc[0][1]);
        DP(xr0.x, w0.z, acc[0][2]); DP(xr0.y, w1.z, acc[0][2]); DP(xr0.z, w2.z, acc[0][2]); DP(xr0.w, w3.z, acc[0][2]);
        DP(xr0.x, w0.w, acc[0][3]); DP(xr0.y, w1.w, acc[0][3]); DP(xr0.z, w2.w, acc[0][3]); DP(xr0.w, w3.w, acc[0][3]);
        DP(xr1.x, w0.x, acc[1][0]); DP(xr1.y, w1.x, acc[1][0]); DP(xr1.z, w2.x, acc[1][0]); DP(xr1.w, w3.x, acc[1][0]);
        DP(xr1.x, w0.y, acc[1][1]); DP(xr1.y, w1.y, acc[1][1]); DP(xr1.z, w2.y, acc[1][1]); DP(xr1.w, w3.y, acc[1][1]);
        DP(xr1.x, w0.z, acc[1][2]); DP(xr1.y, w1.z, acc[1][2]); DP(xr1.z, w2.z, acc[1][2]); DP(xr1.w, w3.z, acc[1][2]);
        DP(xr1.x, w0.w, acc[1][3]); DP(xr1.y, w1.w, acc[1][3]); DP(xr1.z, w2.w, acc[1][3]); DP(xr1.w, w3.w, acc[1][3]);
        DP(xr2.x, w0.x, acc[2][0]); DP(xr2.y, w1.x, acc[2][0]); DP(xr2.z, w2.x, acc[2][0]); DP(xr2.w, w3.x, acc[2][0]);
        DP(xr2.x, w0.y, acc[2][1]); DP(xr2.y, w1.y, acc[2][1]); DP(xr2.z, w2.y, acc[2][1]); DP(xr2.w, w3.y, acc[2][1]);
        DP(xr2.x, w0.z, acc[2][2]); DP(xr2.y, w1.z, acc[2][2]); DP(xr2.z, w2.z, acc[2][2]); DP(xr2.w, w3.z, acc[2][2]);
        DP(xr2.x, w0.w, acc[2][3]); DP(xr2.y, w1.w, acc[2][3]); DP(xr2.z, w2.w, acc[2][3]); DP(xr2.w, w3.w, acc[2][3]);
        DP(xr3.x, w0.x, acc[3][0]); DP(xr3.y, w1.x, acc[3][0]); DP(xr3.z, w2.x, acc[3][0]); DP(xr3.w, w3.x, acc[3][0]);
        DP(xr3.x, w0.y, acc[3][1]); DP(xr3.y, w1.y, acc[3][1]); DP(xr3.z, w2.y, acc[3][1]); DP(xr3.w, w3.y, acc[3][1]);
        DP(xr3.x, w0.z, acc[3][2]); DP(xr3.y, w1.z, acc[3][2]); DP(xr3.z, w2.z, acc[3][2]); DP(xr3.w, w3.z, acc[3][2]);
        DP(xr3.x, w0.w, acc[3][3]); DP(xr3.y, w1.w, acc[3][3]); DP(xr3.z, w2.w, acc[3][3]); DP(xr3.w, w3.w, acc[3][3]);
    }
}

// ---------------- kernel 3: Q + K/V projections in one launch ----------------
// blocks [0, 2048): Q rows; [2048, 2176): K rows; [2176, 2304): V rows
__global__ __launch_bounds__(256) void k_proj(const float* x, const float* qb,
                                              const float* kb, const float* vb,
                                              float* out) {
    __shared__ unsigned xq_s[32 * 32];
    __shared__ unsigned wq_s[32 * 128];
    int blk = blockIdx.x;
    float amax = __uint_as_float(g_amax_x);
    float is_inv = __fdiv_rn(127.0f, amax);
    float is = amax * (1.0f / 127.0f);
    int warp = threadIdx.x >> 5, lane = threadIdx.x & 31;
    int c0 = lane * 4;
    int acc[4][4];

    if (blk < 2048) {  // ---- Q ---- (pre-scaled by 0.25*log2e for exp2-domain attn)
        int row0 = blk * 32;
        float sc = g_ws[0] * is;
        bitgemm_core(x + (size_t)row0 * 128, g_wq[0], is_inv, xq_s, wq_s, acc);
        float4 bias = *(const float4*)(qb + c0);
#pragma unroll
        for (int rr = 0; rr < 4; rr++) {
            int r = row0 + warp * 4 + rr;
            float4 o;
            o.x = ((float)acc[rr][0] * sc + bias.x) * QSCALE;
            o.y = ((float)acc[rr][1] * sc + bias.y) * QSCALE;
            o.z = ((float)acc[rr][2] * sc + bias.z) * QSCALE;
            o.w = ((float)acc[rr][3] * sc + bias.w) * QSCALE;
            *(float4*)(g_q + (size_t)r * 128 + c0) = o;
        }
    } else {  // ---- K or V, last 128 tokens of each batch ----
        int which = (blk >= 2176) ? 1 : 0;
        int row0 = (blk - (which ? 2176 : 2048)) * 32;  // r in [0,4096)
        int b = row0 >> 7, i0 = row0 & 127;
        const float* xbase = x + (((size_t)b * SS) + (SS - WINDOW) + i0) * EE;
        float sc = g_ws[1 + which] * is;
        const float* bias_p = which ? vb : kb;
        size_t base = which ? (size_t)VOFF : (size_t)KOFF;
        bitgemm_core(xbase, g_wq[1 + which], is_inv, xq_s, wq_s, acc);
        float4 bias = *(const float4*)(bias_p + c0);
        int h = c0 >> 4, d0 = c0 & 15;
#pragma unroll
        for (int rr = 0; rr < 4; rr++) {
            int r = row0 + warp * 4 + rr;
            int b2 = r >> 7, ii = r & 127;
            float4 o;
            o.x = (float)acc[rr][0] * sc + bias.x;
            o.y = (float)acc[rr][1] * sc + bias.y;
            o.z = (float)acc[rr][2] * sc + bias.z;
            o.w = (float)acc[rr][3] * sc + bias.w;
            *(float4*)(out + base + (((size_t)(b2 * HH + h)) * WINDOW + ii) * DD + d0) = o;
        }
    }
}

// ---------------- attention inner machinery (no-max softmax, exp2 domain) ----
#define NEG_INF __int_as_float(0xff800000)

struct AttState {
    unsigned long long q[8];
    unsigned long long a[8];
};

__device__ __forceinline__ void att_load_q(AttState& st, const float* qptr) {
    const ulonglong2* qp = (const ulonglong2*)qptr;
    ulonglong2 q01 = qp[0], q23 = qp[1], q45 = qp[2], q67 = qp[3];
    st.q[0] = q01.x; st.q[1] = q01.y; st.q[2] = q23.x; st.q[3] = q23.y;
    st.q[4] = q45.x; st.q[5] = q45.y; st.q[6] = q67.x; st.q[7] = q67.y;
#pragma unroll
    for (int i = 0; i < 8; i++) st.a[i] = 0ull;
}

__device__ __forceinline__ float att_score(const AttState& st,
                                           const ulonglong2& kA, const ulonglong2& kB,
                                           const ulonglong2& kC, const ulonglong2& kD) {
    unsigned long long d0 = f2_mul(st.q[0], kA.x);
    unsigned long long d1 = f2_mul(st.q[1], kA.y);
    d0 = f2_fma(st.q[2], kB.x, d0);
    d1 = f2_fma(st.q[3], kB.y, d1);
    d0 = f2_fma(st.q[4], kC.x, d0);
    d1 = f2_fma(st.q[5], kC.y, d1);
    d0 = f2_fma(st.q[6], kD.x, d0);
    d1 = f2_fma(st.q[7], kD.y, d1);
    float2 ds = f2_unpack(f2_add(d0, d1));
    return ds.x + ds.y;  // log2-domain score (q pre-scaled by 0.25*log2e)
}

// accumulate 8 output dims starting at a[base] from two V quads
__device__ __forceinline__ void accum_h(AttState& st, int base, unsigned long long p2,
                                        const ulonglong2& vA, const ulonglong2& vB) {
    st.a[base + 0] = f2_fma(p2, vA.x, st.a[base + 0]);
    st.a[base + 1] = f2_fma(p2, vA.y, st.a[base + 1]);
    st.a[base + 2] = f2_fma(p2, vB.x, st.a[base + 2]);
    st.a[base + 3] = f2_fma(p2, vB.y, st.a[base + 3]);
}

__device__ __forceinline__ float att_finish(AttState& st, float l, float* optr) {
    float inv = 1.0f / l;
    unsigned long long inv2 = f2_pack(inv, inv);
    float mx = 0.f;
#pragma unroll
    for (int i = 0; i < 8; i++) {
        st.a[i] = f2_mul(st.a[i], inv2);
        float2 u = f2_unpack(st.a[i]);
        mx = fmaxf(mx, fmaxf(fabsf(u.x), fabsf(u.y)));
    }
    ulonglong2* op = (ulonglong2*)optr;
    op[0] = make_ulonglong2(st.a[0], st.a[1]);
    op[1] = make_ulonglong2(st.a[2], st.a[3]);
    op[2] = make_ulonglong2(st.a[4], st.a[5]);
    op[3] = make_ulonglong2(st.a[6], st.a[7]);
    return mx;
}

// ---------------- kernel 5: attention, 256 thr, 3 q/thread, lb(256,2) --------
// grid: (3, H, B). Block chunk covers queries [chunk*768, chunk*768+768).
// Thread t: s0 = chunk*768+t, s1 = s0+256, s2 = s0+512.
// chunk==2: s2 would be >= 2048, so that block runs a 2-query variant.
__global__ __launch_bounds__(256, 2) void k_attn(const float* cached_k, const float* cached_v,
                                                 const float* outbuf) {
    __shared__ __align__(16) float ks[KTOT * DD];
    __shared__ __align__(16) float vs[KTOT * DD];
    int b = blockIdx.z, h = blockIdx.y, chunk = blockIdx.x;
    int t = threadIdx.x;
    size_t bh = (size_t)(b * HH + h);
    {
        // vectorized fill: sinks (4 rows = 16 float4), window (128 rows = 512 float4)
        const float4* kc4 = (const float4*)(cached_k + bh * CACHE * DD);
        const float4* vc4 = (const float4*)(cached_v + bh * CACHE * DD);
        const float4* kn4 = (const float4*)(outbuf + KOFF + bh * WINDOW * DD);
        const float4* vn4 = (const float4*)(outbuf + VOFF + bh * WINDOW * DD);
        float4* ks4 = (float4*)ks;
        float4* vs4 = (float4*)vs;
        if (t < 16) {
            ks4[t] = kc4[t];
            vs4[t] = vc4[t];
        }
#pragma unroll
        for (int i = 0; i < 2; i++) {
            int idx = t + i * 256;
            ks4[16 + idx] = kn4[idx];
            vs4[16 + idx] = vn4[idx];
        }
    }
    __syncthreads();

    int s0 = chunk * 768 + t;
    int s1 = s0 + 256;
    int s2 = s0 + 512;
    const float* qbase = g_q + ((size_t)b * SS) * HD + h * DD;
    const ulonglong2* k2 = (const ulonglong2*)ks;
    const ulonglong2* v2 = (const ulonglong2*)vs;
    float* aob = g_ao + ((size_t)b * SS) * HD + h * DD;

    if (chunk == 2) {
        // 2-query variant: s0 in [1536,1791], s1 in [1792,2047] — all full
        AttState st0, st1;
        att_load_q(st0, qbase + (size_t)s0 * HD);
        att_load_q(st1, qbase + (size_t)s1 * HD);
        float l0 = 0.f, l1 = 0.f;
#pragma unroll 2
        for (int j = 0; j < KTOT; j++) {
            ulonglong2 kA = k2[j * 4 + 0], kB = k2[j * 4 + 1];
            ulonglong2 kC = k2[j * 4 + 2], kD = k2[j * 4 + 3];
            float sc0 = att_score(st0, kA, kB, kC, kD);
            float sc1 = att_score(st1, kA, kB, kC, kD);
            float p0 = fast_ex2(sc0);
            float p1 = fast_ex2(sc1);
            l0 += p0; l1 += p1;
            unsigned long long P0 = f2_pack(p0, p0);
            unsigned long long P1 = f2_pack(p1, p1);
            {
                ulonglong2 vA = v2[j * 4 + 0], vB = v2[j * 4 + 1];
                accum_h(st0, 0, P0, vA, vB);
                accum_h(st1, 0, P1, vA, vB);
            }
            {
                ulonglong2 vC = v2[j * 4 + 2], vD = v2[j * 4 + 3];
                accum_h(st0, 4, P0, vC, vD);
                accum_h(st1, 4, P1, vC, vD);
            }
        }
        float mx = fmaxf(att_finish(st0, l0, aob + (size_t)s0 * HD),
                         att_finish(st1, l1, aob + (size_t)s1 * HD));
        for (int o = 16; o; o >>= 1) mx = fmaxf(mx, __shfl_xor_sync(0xFFFFFFFFu, mx, o));
        if ((t & 31) == 0) atomicMax(&g_amax_o, __float_as_uint(mx));
    } else {
        // 3-query variant (chunk 0 or 1); chunk 0 masks q0's causal raggedness
        AttState st0, st1, st2;
        att_load_q(st0, qbase + (size_t)s0 * HD);
        att_load_q(st1, qbase + (size_t)s1 * HD);
        att_load_q(st2, qbase + (size_t)s2 * HD);
        float l0 = 0.f, l1 = 0.f, l2v = 0.f;
        if (chunk == 0) {
            int jmax0 = min(s0, KTOT - 1);  // s1,s2 >= 256 are full
            for (int j = 0; j < KTOT; j++) {
                ulonglong2 kA = k2[j * 4 + 0], kB = k2[j * 4 + 1];
                ulonglong2 kC = k2[j * 4 + 2], kD = k2[j * 4 + 3];
                float sc0 = att_score(st0, kA, kB, kC, kD);
                float sc1 = att_score(st1, kA, kB, kC, kD);
                float sc2 = att_score(st2, kA, kB, kC, kD);
                sc0 = (j <= jmax0) ? sc0 : NEG_INF;  // ex2(-inf)=0 contribution
                float p0 = fast_ex2(sc0);
                float p1 = fast_ex2(sc1);
                float p2 = fast_ex2(sc2);
                l0 += p0; l1 += p1; l2v += p2;
                unsigned long long P0 = f2_pack(p0, p0);
                unsigned long long P1 = f2_pack(p1, p1);
                unsigned long long P2 = f2_pack(p2, p2);
                {
                    ulonglong2 vA = v2[j * 4 + 0], vB = v2[j * 4 + 1];
                    accum_h(st0, 0, P0, vA, vB);
                    accum_h(st1, 0, P1, vA, vB);
                    accum_h(st2, 0, P2, vA, vB);
                }
                {
                    ulonglong2 vC = v2[j * 4 + 2], vD = v2[j * 4 + 3];
                    accum_h(st0, 4, P0, vC, vD);
                    accum_h(st1, 4, P1, vC, vD);
                    accum_h(st2, 4, P2, vC, vD);
                }
            }
        } else {
#pragma unroll 2
            for (int j = 0; j < KTOT; j++) {
                ulonglong2 kA = k2[j * 4 + 0], kB = k2[j * 4 + 1];
                ulonglong2 kC = k2[j * 4 + 2], kD = k2[j * 4 + 3];
                float sc0 = att_score(st0, kA, kB, kC, kD);
                float sc1 = att_score(st1, kA, kB, kC, kD);
                float sc2 = att_score(st2, kA, kB, kC, kD);
                float p0 = fast_ex2(sc0);
                float p1 = fast_ex2(sc1);
                float p2 = fast_ex2(sc2);
                l0 += p0; l1 += p1; l2v += p2;
                unsigned long long P0 = f2_pack(p0, p0);
                unsigned long long P1 = f2_pack(p1, p1);
                unsigned long long P2 = f2_pack(p2, p2);
                {
                    ulonglong2 vA = v2[j * 4 + 0], vB = v2[j * 4 + 1];
                    accum_h(st0, 0, P0, vA, vB);
                    accum_h(st1, 0, P1, vA, vB);
                    accum_h(st2, 0, P2, vA, vB);
                }
                {
                    ulonglong2 vC = v2[j * 4 + 2], vD = v2[j * 4 + 3];
                    accum_h(st0, 4, P0, vC, vD);
                    accum_h(st1, 4, P1, vC, vD);
                    accum_h(st2, 4, P2, vC, vD);
                }
            }
        }
        float mx = fmaxf(att_finish(st0, l0, aob + (size_t)s0 * HD),
                         att_finish(st1, l1, aob + (size_t)s1 * HD));
        mx = fmaxf(mx, att_finish(st2, l2v, aob + (size_t)s2 * HD));
        for (int o = 16; o; o >>= 1) mx = fmaxf(mx, __shfl_xor_sync(0xFFFFFFFFu, mx, o));
        if ((t & 31) == 0) atomicMax(&g_amax_o, __float_as_uint(mx));
    }
}

// ---------------- kernel 6: O projection ----------------
__global__ __launch_bounds__(256) void k_oproj(const float* ob, float* out) {
    __shared__ unsigned xq_s[32 * 32];
    __shared__ unsigned wq_s[32 * 128];
    int row0 = blockIdx.x * 32;
    float amax = __uint_as_float(g_amax_o);
    float is_inv = __fdiv_rn(127.0f, amax);
    float sc = g_ws[3] * (amax * (1.0f / 127.0f));
    int acc[4][4];
    bitgemm_core(g_ao + (size_t)row0 * 128, g_wq[3], is_inv, xq_s, wq_s, acc);
    int warp = threadIdx.x >> 5, lane = threadIdx.x & 31;
    int c0 = lane * 4;
    float4 bias = *(const float4*)(ob + c0);
#pragma unroll
    for (int rr = 0; rr < 4; rr++) {
        int r = row0 + warp * 4 + rr;
        float4 o;
        o.x = (float)acc[rr][0] * sc + bias.x;
        o.y = (float)acc[rr][1] * sc + bias.y;
        o.z = (float)acc[rr][2] * sc + bias.z;
        o.w = (float)acc[rr][3] * sc + bias.w;
        *(float4*)(out + (size_t)r * 128 + c0) = o;
    }
}

// ---------------- launcher ----------------
extern "C" void kernel_launch(void* const* d_in, const int* in_sizes, int n_in,
                              void* d_out, int out_size) {
    const float* x  = (const float*)d_in[0];
    const float* ck = (const float*)d_in[1];
    const float* cv = (const float*)d_in[2];
    const float* qb = (const float*)d_in[4];
    const float* kb = (const float*)d_in[6];
    const float* vb = (const float*)d_in[8];
    const float* ob = (const float*)d_in[10];
    const float* qw = (const float*)d_in[3];
    const float* kw = (const float*)d_in[5];
    const float* vw = (const float*)d_in[7];
    const float* ow = (const float*)d_in[9];
    float* out = (float*)d_out;

    k_prep<<<4, 256>>>(qw, kw, vw, ow);
    k_amax<<<1024, 256>>>(x, (BB * SS * EE) / 4);
    k_proj<<<2048 + 256, 256>>>(x, qb, kb, vb, out);
    k_attn<<<dim3(3, HH, BB), 256>>>(ck, cv, out);
    k_oproj<<<(BB * SS) / 32, 256>>>(ob, out);
}

// round 17
// speedup vs baseline: 1.2928x; 1.1585x over previous
#include <cuda_runtime.h>
#include <cstdint>

#define BB 32
#define SS 2048
#define EE 128
#define HH 8
#define DD 16
#define HD 128
#define KTOT 132
#define CACHE 256
#define WINDOW 128
#define SINKS 4

// d_out layout: [output (B*S*HD)] [new_k (B*H*128*16)] [new_v (B*H*128*16)]
#define OUT_ELEMS (BB * SS * HD)            // 8388608
#define KOFF OUT_ELEMS                      // 8388608
#define VOFF (KOFF + BB * HH * WINDOW * DD) // 8912896

// ---------------- scratch (device globals; no allocation APIs) ----------------
// g_q is pre-scaled by 0.25 * log2(e) so attention probs = exp2(q'.k)
__device__ float    g_q[(size_t)BB * SS * HD];        // 33.5 MB, layout (b,s,h*d)
__device__ float    g_ao[(size_t)BB * SS * HD];       // 33.5 MB, layout (b,s,h*d)
__device__ unsigned g_wq[4][32 * 128];                // packed ternary weights (q,k,v,o)
__device__ float    g_ws[4];                          // w_scale per weight
__device__ unsigned g_amax_x;
__device__ unsigned g_amax_o;

#define QSCALE 0.3606737602222409f  /* 0.25 * log2(e) */
#define NEG_INF __int_as_float(0xff800000)

// ---------------- f32x2 packed-math helpers (sm_103a) ----------------
__device__ __forceinline__ unsigned long long f2_mul(unsigned long long a, unsigned long long b) {
    unsigned long long d;
    asm("mul.rn.f32x2 %0,%1,%2;" : "=l"(d) : "l"(a), "l"(b));
    return d;
}
__device__ __forceinline__ unsigned long long f2_fma(unsigned long long a, unsigned long long b,
                                                     unsigned long long c) {
    unsigned long long d;
    asm("fma.rn.f32x2 %0,%1,%2,%3;" : "=l"(d) : "l"(a), "l"(b), "l"(c));
    return d;
}
__device__ __forceinline__ unsigned long long f2_add(unsigned long long a, unsigned long long b) {
    unsigned long long d;
    asm("add.rn.f32x2 %0,%1,%2;" : "=l"(d) : "l"(a), "l"(b));
    return d;
}
__device__ __forceinline__ unsigned long long f2_pack(float lo, float hi) {
    unsigned long long d;
    asm("mov.b64 %0,{%1,%2};" : "=l"(d) : "f"(lo), "f"(hi));
    return d;
}
__device__ __forceinline__ float2 f2_unpack(unsigned long long v) {
    float2 r;
    asm("mov.b64 {%0,%1},%2;" : "=f"(r.x), "=f"(r.y) : "l"(v));
    return r;
}
__device__ __forceinline__ float fast_ex2(float x) {
    float r;
    asm("ex2.approx.ftz.f32 %0,%1;" : "=f"(r) : "f"(x));
    return r;
}

// s8 x s8 -> s32 mma: D(16x8) = A(16x32) x B(32x8) + C, bit-exact integer
__device__ __forceinline__ void imma16832(int& c0, int& c1, int& c2, int& c3,
                                          unsigned a0, unsigned a1, unsigned a2, unsigned a3,
                                          unsigned b0, unsigned b1) {
    asm volatile(
        "mma.sync.aligned.m16n8k32.row.col.s32.s8.s8.s32 "
        "{%0,%1,%2,%3}, {%4,%5,%6,%7}, {%8,%9}, {%0,%1,%2,%3};"
        : "+r"(c0), "+r"(c1), "+r"(c2), "+r"(c3)
        : "r"(a0), "r"(a1), "r"(a2), "r"(a3), "r"(b0), "r"(b1));
}

// ---------------- helpers ----------------
__device__ __forceinline__ unsigned quant4(float4 v, float is_inv) {
    int a = __float2int_rn(fminf(fmaxf(v.x * is_inv, -128.f), 127.f));
    int b = __float2int_rn(fminf(fmaxf(v.y * is_inv, -128.f), 127.f));
    int c = __float2int_rn(fminf(fmaxf(v.z * is_inv, -128.f), 127.f));
    int d = __float2int_rn(fminf(fmaxf(v.w * is_inv, -128.f), 127.f));
    return (unsigned)(a & 0xFF) | ((unsigned)(b & 0xFF) << 8) |
           ((unsigned)(c & 0xFF) << 16) | ((unsigned)(d & 0xFF) << 24);
}

// ---------------- kernel 1: w_scale + ternarize + pack (4 blocks) + init -----
__global__ __launch_bounds__(256) void k_prep(const float* qw, const float* kw,
                                              const float* vw, const float* ow) {
    int bw = blockIdx.x;
    if (bw == 0 && threadIdx.x == 0) { g_amax_x = 0u; g_amax_o = 0u; }
    const float* w = (bw == 0) ? qw : (bw == 1) ? kw : (bw == 2) ? vw : ow;
    __shared__ float red[256];
    __shared__ float ws_s;
    int t = threadIdx.x;
    float s = 0.f;
    for (int i = t; i < 16384; i += 256) s += fabsf(w[i]);
    red[t] = s;
    __syncthreads();
    for (int o = 128; o > 0; o >>= 1) {
        if (t < o) red[t] += red[t + o];
        __syncthreads();
    }
    if (t == 0) { ws_s = red[0] / 16384.0f; g_ws[bw] = ws_s; }
    __syncthreads();
    float thr = 0.5f * ws_s;
    int c = t >> 1, half = t & 1;
    for (int i = 0; i < 16; i++) {
        int kk = half * 16 + i;
        float4 wv = *(const float4*)(w + c * 128 + kk * 4);
        int t0 = (fabsf(wv.x) > thr) ? (wv.x > 0.f ? 1 : -1) : 0;
        int t1 = (fabsf(wv.y) > thr) ? (wv.y > 0.f ? 1 : -1) : 0;
        int t2 = (fabsf(wv.z) > thr) ? (wv.z > 0.f ? 1 : -1) : 0;
        int t3 = (fabsf(wv.w) > thr) ? (wv.w > 0.f ? 1 : -1) : 0;
        unsigned p = (unsigned)(t0 & 0xFF) | ((unsigned)(t1 & 0xFF) << 8) |
                     ((unsigned)(t2 & 0xFF) << 16) | ((unsigned)(t3 & 0xFF) << 24);
        g_wq[bw][kk * 128 + c] = p;
    }
}

// ---------------- kernel 2: abs-max over x ----------------
__global__ __launch_bounds__(256) void k_amax(const float* x, int n4) {
    int idx = blockIdx.x * blockDim.x + threadIdx.x;
    int stride = gridDim.x * blockDim.x;
    float m = 0.f;
    const float4* x4 = (const float4*)x;
    for (int i = idx; i < n4; i += stride) {
        float4 v = x4[i];
        m = fmaxf(m, fmaxf(fmaxf(fabsf(v.x), fabsf(v.y)), fmaxf(fabsf(v.z), fabsf(v.w))));
    }
    for (int o = 16; o; o >>= 1) m = fmaxf(m, __shfl_xor_sync(0xFFFFFFFFu, m, o));
    if ((threadIdx.x & 31) == 0) atomicMax(&g_amax_x, __float_as_uint(m));
}

// ---------------- shared GEMM core: 32 rows x 128 cols via s8 IMMA ----------
// 256 threads = 8 warps. warp w: row-tile rt = w&1 (16 rows), col-group (w>>1)*32.
// Each warp: 4 n-tiles x 4 k-steps = 16 mmas. Exact integers == dp4a result.
// xq_s stride 36 words (16B-aligned rows, conflict-free A loads);
// wq_s stride 136 words (conflict-free B loads).
#define XQS (32 * 36)
#define WQS (32 * 136)

__device__ __forceinline__ void bitgemm_mma(const float* xbase, const unsigned* wq_g,
                                            float is_inv, unsigned* xq_s, unsigned* wq_s,
                                            int (&acc)[4][4]) {
    int t = threadIdx.x;
    {
        int row = t >> 3, seg = t & 7;
        const float4* src = (const float4*)(xbase + row * 128 + seg * 16);
        uint4 pk;
        pk.x = quant4(src[0], is_inv);
        pk.y = quant4(src[1], is_inv);
        pk.z = quant4(src[2], is_inv);
        pk.w = quant4(src[3], is_inv);
        *(uint4*)(xq_s + row * 36 + seg * 4) = pk;
    }
    {
        // stage ALL 32*128 = 4096 weight words (1024 uint4s) into padded smem
        const uint4* src4 = (const uint4*)wq_g;
#pragma unroll
        for (int i = 0; i < 4; i++) {
            int idx4 = t + i * 256;            // 0..1023
            int kk = idx4 >> 5;                // word>>7
            int c = (idx4 << 2) & 127;         // 4-aligned column
            *(uint4*)(wq_s + kk * 136 + c) = src4[idx4];
        }
    }
    __syncthreads();

    int warp = t >> 5, lane = t & 31;
    int rt = warp & 1, cb = (warp >> 1) * 32;
    int g = lane >> 2, tig = lane & 3;
#pragma unroll
    for (int nt = 0; nt < 4; nt++)
#pragma unroll
        for (int i = 0; i < 4; i++) acc[nt][i] = 0;

#pragma unroll
    for (int ks = 0; ks < 4; ks++) {
        int r0 = rt * 16 + g;
        unsigned a0 = xq_s[r0 * 36 + ks * 8 + tig];
        unsigned a1 = xq_s[(r0 + 8) * 36 + ks * 8 + tig];
        unsigned a2 = xq_s[r0 * 36 + ks * 8 + tig + 4];
        unsigned a3 = xq_s[(r0 + 8) * 36 + ks * 8 + tig + 4];
#pragma unroll
        for (int nt = 0; nt < 4; nt++) {
            int col = cb + nt * 8 + g;
            unsigned b0 = wq_s[(ks * 8 + tig) * 136 + col];
            unsigned b1 = wq_s[(ks * 8 + tig + 4) * 136 + col];
            imma16832(acc[nt][0], acc[nt][1], acc[nt][2], acc[nt][3],
                      a0, a1, a2, a3, b0, b1);
        }
    }
    // C fragment: acc[nt][0..1] = row (row0+rt*16+g), cols cb+nt*8+2*tig, +1
    //             acc[nt][2..3] = row +8, same cols
}

// ---------------- kernel 3: Q + K/V projections in one launch ----------------
// blocks [0, 2048): Q rows; [2048, 2176): K rows; [2176, 2304): V rows
__global__ __launch_bounds__(256) void k_proj(const float* x, const float* qb,
                                              const float* kb, const float* vb,
                                              float* out) {
    __shared__ unsigned xq_s[XQS];
    __shared__ unsigned wq_s[WQS];
    int blk = blockIdx.x;
    float amax = __uint_as_float(g_amax_x);
    float is_inv = __fdiv_rn(127.0f, amax);
    float is = amax * (1.0f / 127.0f);
    int warp = threadIdx.x >> 5, lane = threadIdx.x & 31;
    int rt = warp & 1, cb = (warp >> 1) * 32;
    int g = lane >> 2, tig = lane & 3;
    int acc[4][4];

    if (blk < 2048) {  // ---- Q ---- (pre-scaled by 0.25*log2e for exp2-domain attn)
        int row0 = blk * 32;
        float sc = g_ws[0] * is;
        bitgemm_mma(x + (size_t)row0 * 128, g_wq[0], is_inv, xq_s, wq_s, acc);
        int rA = row0 + rt * 16 + g, rB = rA + 8;
#pragma unroll
        for (int nt = 0; nt < 4; nt++) {
            int c0 = cb + nt * 8 + 2 * tig;
            float2 bias = *(const float2*)(qb + c0);
            float2 oA, oB;
            oA.x = ((float)acc[nt][0] * sc + bias.x) * QSCALE;
            oA.y = ((float)acc[nt][1] * sc + bias.y) * QSCALE;
            oB.x = ((float)acc[nt][2] * sc + bias.x) * QSCALE;
            oB.y = ((float)acc[nt][3] * sc + bias.y) * QSCALE;
            *(float2*)(g_q + (size_t)rA * 128 + c0) = oA;
            *(float2*)(g_q + (size_t)rB * 128 + c0) = oB;
        }
    } else {  // ---- K or V, last 128 tokens of each batch ----
        int which = (blk >= 2176) ? 1 : 0;
        int row0 = (blk - (which ? 2176 : 2048)) * 32;  // r in [0,4096)
        int b = row0 >> 7, i0 = row0 & 127;
        const float* xbase = x + (((size_t)b * SS) + (SS - WINDOW) + i0) * EE;
        float sc = g_ws[1 + which] * is;
        const float* bias_p = which ? vb : kb;
        size_t base = which ? (size_t)VOFF : (size_t)KOFF;
        bitgemm_mma(xbase, g_wq[1 + which], is_inv, xq_s, wq_s, acc);
        int rA = row0 + rt * 16 + g, rB = rA + 8;
        int bA = rA >> 7, iA = rA & 127;
        int bB = rB >> 7, iB = rB & 127;
#pragma unroll
        for (int nt = 0; nt < 4; nt++) {
            int c0 = cb + nt * 8 + 2 * tig;
            int h = c0 >> 4, d0 = c0 & 15;
            float2 bias = *(const float2*)(bias_p + c0);
            float2 oA, oB;
            oA.x = (float)acc[nt][0] * sc + bias.x;
            oA.y = (float)acc[nt][1] * sc + bias.y;
            oB.x = (float)acc[nt][2] * sc + bias.x;
            oB.y = (float)acc[nt][3] * sc + bias.y;
            *(float2*)(out + base + (((size_t)(bA * HH + h)) * WINDOW + iA) * DD + d0) = oA;
            *(float2*)(out + base + (((size_t)(bB * HH + h)) * WINDOW + iB) * DD + d0) = oB;
        }
    }
}

// ---------------- attention inner machinery (no-max softmax, exp2 domain) ----
struct AttState {
    unsigned long long q[8];
    unsigned long long a[8];
    float l;
};

__device__ __forceinline__ void att_load_q(AttState& st, const float* qptr) {
    const ulonglong2* qp = (const ulonglong2*)qptr;
    ulonglong2 q01 = qp[0], q23 = qp[1], q45 = qp[2], q67 = qp[3];
    st.q[0] = q01.x; st.q[1] = q01.y; st.q[2] = q23.x; st.q[3] = q23.y;
    st.q[4] = q45.x; st.q[5] = q45.y; st.q[6] = q67.x; st.q[7] = q67.y;
#pragma unroll
    for (int i = 0; i < 8; i++) st.a[i] = 0ull;
    st.l = 0.f;
}

__device__ __forceinline__ float att_score(const AttState& st,
                                           const ulonglong2& kA, const ulonglong2& kB,
                                           const ulonglong2& kC, const ulonglong2& kD) {
    unsigned long long d0 = f2_mul(st.q[0], kA.x);
    unsigned long long d1 = f2_mul(st.q[1], kA.y);
    d0 = f2_fma(st.q[2], kB.x, d0);
    d1 = f2_fma(st.q[3], kB.y, d1);
    d0 = f2_fma(st.q[4], kC.x, d0);
    d1 = f2_fma(st.q[5], kC.y, d1);
    d0 = f2_fma(st.q[6], kD.x, d0);
    d1 = f2_fma(st.q[7], kD.y, d1);
    float2 ds = f2_unpack(f2_add(d0, d1));
    return ds.x + ds.y;  // log2-domain score (q pre-scaled by 0.25*log2e)
}

__device__ __forceinline__ void att_update(AttState& st, float sc,
                                           const ulonglong2& vA, const ulonglong2& vB,
                                           const ulonglong2& vC, const ulonglong2& vD) {
    float p = fast_ex2(sc);  // scores bounded ~|12|; no overflow possible
    unsigned long long p2 = f2_pack(p, p);
    st.l += p;
    st.a[0] = f2_fma(p2, vA.x, st.a[0]);
    st.a[1] = f2_fma(p2, vA.y, st.a[1]);
    st.a[2] = f2_fma(p2, vB.x, st.a[2]);
    st.a[3] = f2_fma(p2, vB.y, st.a[3]);
    st.a[4] = f2_fma(p2, vC.x, st.a[4]);
    st.a[5] = f2_fma(p2, vC.y, st.a[5]);
    st.a[6] = f2_fma(p2, vD.x, st.a[6]);
    st.a[7] = f2_fma(p2, vD.y, st.a[7]);
}

__device__ __forceinline__ float att_finish(AttState& st, float* optr) {
    float inv = 1.0f / st.l;
    unsigned long long inv2 = f2_pack(inv, inv);
    float mx = 0.f;
#pragma unroll
    for (int i = 0; i < 8; i++) {
        st.a[i] = f2_mul(st.a[i], inv2);
        float2 u = f2_unpack(st.a[i]);
        mx = fmaxf(mx, fmaxf(fabsf(u.x), fabsf(u.y)));
    }
    ulonglong2* op = (ulonglong2*)optr;
    op[0] = make_ulonglong2(st.a[0], st.a[1]);
    op[1] = make_ulonglong2(st.a[2], st.a[3]);
    op[2] = make_ulonglong2(st.a[4], st.a[5]);
    op[3] = make_ulonglong2(st.a[6], st.a[7]);
    return mx;
}

// ---------------- kernel 5: attention, 2 queries/thread, f32x2, branch-free --
// grid: (SS/512, H, B), 256 threads. Thread t handles queries chunk*512+t and +256.
__global__ __launch_bounds__(256, 2) void k_attn(const float* cached_k, const float* cached_v,
                                                 const float* outbuf) {
    __shared__ __align__(16) float ks[KTOT * DD];
    __shared__ __align__(16) float vs[KTOT * DD];
    int b = blockIdx.z, h = blockIdx.y, chunk = blockIdx.x;
    int t = threadIdx.x;
    size_t bh = (size_t)(b * HH + h);
    {
        const float* knew = outbuf + KOFF + bh * WINDOW * DD;
        const float* vnew = outbuf + VOFF + bh * WINDOW * DD;
        const float* kc = cached_k + bh * CACHE * DD;
        const float* vc = cached_v + bh * CACHE * DD;
        for (int i = t; i < KTOT * DD; i += 256) {
            int j = i >> 4;
            ks[i] = (j < SINKS) ? kc[i] : knew[i - SINKS * DD];
            vs[i] = (j < SINKS) ? vc[i] : vnew[i - SINKS * DD];
        }
    }
    __syncthreads();

    int s0 = chunk * 512 + t;
    int s1 = s0 + 256;
    const float* qbase = g_q + ((size_t)b * SS) * HD + h * DD;
    AttState st0, st1;
    att_load_q(st0, qbase + (size_t)s0 * HD);
    att_load_q(st1, qbase + (size_t)s1 * HD);

    const ulonglong2* k2 = (const ulonglong2*)ks;
    const ulonglong2* v2 = (const ulonglong2*)vs;

    if (chunk != 0) {
        // full: both queries attend to all 132 keys
#pragma unroll 2
        for (int j = 0; j < KTOT; j++) {
            ulonglong2 kA = k2[j * 4 + 0], kB = k2[j * 4 + 1];
            ulonglong2 kC = k2[j * 4 + 2], kD = k2[j * 4 + 3];
            float sc0 = att_score(st0, kA, kB, kC, kD);
            float sc1 = att_score(st1, kA, kB, kC, kD);
            ulonglong2 vA = v2[j * 4 + 0], vB = v2[j * 4 + 1];
            ulonglong2 vC = v2[j * 4 + 2], vD = v2[j * 4 + 3];
            att_update(st0, sc0, vA, vB, vC, vD);
            att_update(st1, sc1, vA, vB, vC, vD);
        }
    } else {
        // chunk 0: query s0 = t in [0,255] may be causal-ragged; s1 >= 256 is full
        int jmax0 = min(s0, KTOT - 1);
        for (int j = 0; j < KTOT; j++) {
            ulonglong2 kA = k2[j * 4 + 0], kB = k2[j * 4 + 1];
            ulonglong2 kC = k2[j * 4 + 2], kD = k2[j * 4 + 3];
            float sc0 = att_score(st0, kA, kB, kC, kD);
            float sc1 = att_score(st1, kA, kB, kC, kD);
            sc0 = (j <= jmax0) ? sc0 : NEG_INF;  // ex2(-inf) = 0 contribution
            ulonglong2 vA = v2[j * 4 + 0], vB = v2[j * 4 + 1];
            ulonglong2 vC = v2[j * 4 + 2], vD = v2[j * 4 + 3];
            att_update(st0, sc0, vA, vB, vC, vD);
            att_update(st1, sc1, vA, vB, vC, vD);
        }
    }

    float* aob = g_ao + ((size_t)b * SS) * HD + h * DD;
    float mx0 = att_finish(st0, aob + (size_t)s0 * HD);
    float mx1 = att_finish(st1, aob + (size_t)s1 * HD);
    float mx = fmaxf(mx0, mx1);
    for (int o = 16; o; o >>= 1) mx = fmaxf(mx, __shfl_xor_sync(0xFFFFFFFFu, mx, o));
    if ((t & 31) == 0) atomicMax(&g_amax_o, __float_as_uint(mx));
}

// ---------------- kernel 6: O projection (s8 IMMA) ----------------
__global__ __launch_bounds__(256) void k_oproj(const float* ob, float* out) {
    __shared__ unsigned xq_s[XQS];
    __shared__ unsigned wq_s[WQS];
    int row0 = blockIdx.x * 32;
    float amax = __uint_as_float(g_amax_o);
    float is_inv = __fdiv_rn(127.0f, amax);
    float sc = g_ws[3] * (amax * (1.0f / 127.0f));
    int acc[4][4];
    bitgemm_mma(g_ao + (size_t)row0 * 128, g_wq[3], is_inv, xq_s, wq_s, acc);
    int warp = threadIdx.x >> 5, lane = threadIdx.x & 31;
    int rt = warp & 1, cb = (warp >> 1) * 32;
    int g = lane >> 2, tig = lane & 3;
    int rA = row0 + rt * 16 + g, rB = rA + 8;
#pragma unroll
    for (int nt = 0; nt < 4; nt++) {
        int c0 = cb + nt * 8 + 2 * tig;
        float2 bias = *(const float2*)(ob + c0);
        float2 oA, oB;
        oA.x = (float)acc[nt][0] * sc + bias.x;
        oA.y = (float)acc[nt][1] * sc + bias.y;
        oB.x = (float)acc[nt][2] * sc + bias.x;
        oB.y = (float)acc[nt][3] * sc + bias.y;
        *(float2*)(out + (size_t)rA * 128 + c0) = oA;
        *(float2*)(out + (size_t)rB * 128 + c0) = oB;
    }
}

// ---------------- launcher ----------------
extern "C" void kernel_launch(void* const* d_in, const int* in_sizes, int n_in,
                              void* d_out, int out_size) {
    const float* x  = (const float*)d_in[0];
    const float* ck = (const float*)d_in[1];
    const float* cv = (const float*)d_in[2];
    const float* qb = (const float*)d_in[4];
    const float* kb = (const float*)d_in[6];
    const float* vb = (const float*)d_in[8];
    const float* ob = (const float*)d_in[10];
    const float* qw = (const float*)d_in[3];
    const float* kw = (const float*)d_in[5];
    const float* vw = (const float*)d_in[7];
    const float* ow = (const float*)d_in[9];
    float* out = (float*)d_out;

    k_prep<<<4, 256>>>(qw, kw, vw, ow);
    k_amax<<<1024, 256>>>(x, (BB * SS * EE) / 4);
    k_proj<<<2048 + 256, 256>>>(x, qb, kb, vb, out);
    k_attn<<<dim3(SS / 512, HH, BB), 256>>>(ck, cv, out);
    k_oproj<<<(BB * SS) / 32, 256>>>(ob, out);
}